// round 9
// baseline (speedup 1.0000x reference)
#include <cuda_runtime.h>

// Problem constants
#define BB 2048
#define TT 200
#define DD 4
#define HH 256
#define GG 1024        // 4*H, gate order i,f,g,o
#define MM 16          // batch rows per CTA
#define NCTA (BB / MM) // 128 CTAs
#define MH 4           // rows per thread (one batch quarter)
#define NTH 1024
#define OO 6
#define HROW 18        // u64 dup-pair slots per h row: 16 used + 2 pad (144B)
#define HS (HH * HROW) // u64 per h buffer
#define NK2 (HH / 2)   // 128 k-pairs

typedef unsigned long long u64;

// k-paired, gate-pair-interleaved weights (see prep): entry [(k2*2+pp)*HH + j]
//  = longlong2 { pack2(w_g0[2k2][j], w_g1[2k2][j]), pack2(w_g0[2k2+1][j], w_g1[2k2+1][j]) }
// pp=0 -> gates (i,f), pp=1 -> gates (g,o)
__device__ longlong2 g_W0p[NK2 * 2 * HH];   // W_hh0
__device__ longlong2 g_W1ip[NK2 * 2 * HH];  // W_ih1
__device__ longlong2 g_W1hp[NK2 * 2 * HH];  // W_hh1
__device__ float g_b0[GG];
__device__ float g_b1[GG];

// ---- packed f32x2 helpers ----
__device__ __forceinline__ u64 fma2(u64 a, u64 b, u64 c) {
    u64 d;
    asm("fma.rn.f32x2 %0, %1, %2, %3;" : "=l"(d) : "l"(a), "l"(b), "l"(c));
    return d;
}
__device__ __forceinline__ u64 pack2(float a, float b) {
    u64 d;
    asm("mov.b64 %0, {%1, %2};" : "=l"(d)
        : "r"(__float_as_uint(a)), "r"(__float_as_uint(b)));
    return d;
}
__device__ __forceinline__ u64 dup2(float v) {
    u64 d;
    unsigned r = __float_as_uint(v);
    asm("mov.b64 %0, {%1, %1};" : "=l"(d) : "r"(r));
    return d;
}
__device__ __forceinline__ void unpack2(u64 v, float& a, float& b) {
    unsigned x, y;
    asm("mov.b64 {%0, %1}, %2;" : "=r"(x), "=r"(y) : "l"(v));
    a = __uint_as_float(x);
    b = __uint_as_float(y);
}
// single-MUFU activations (tanh.approx abs err ~2e-5, budget 1e-3)
__device__ __forceinline__ float tanhx(float x) {
    float y;
    asm("tanh.approx.f32 %0, %1;" : "=f"(y) : "f"(x));
    return y;
}
__device__ __forceinline__ float sigf(float x) {
    return fmaf(tanhx(0.5f * x), 0.5f, 0.5f);
}

// -------- prep: k-paired gate-pair weights + combined biases --------
__global__ void prep_kernel(const float* __restrict__ W_hh0,
                            const float* __restrict__ W_ih1,
                            const float* __restrict__ W_hh1,
                            const float* __restrict__ b_ih0,
                            const float* __restrict__ b_hh0,
                            const float* __restrict__ b_ih1,
                            const float* __restrict__ b_hh1) {
    int idx = blockIdx.x * blockDim.x + threadIdx.x;
    int stride = gridDim.x * blockDim.x;
    for (int t = idx; t < NK2 * 2 * HH; t += stride) {
        int j = t & (HH - 1);
        int pp = (t >> 8) & 1;
        int k2 = t >> 9;
        int g0 = 2 * pp * HH + j;  // gate i (pp=0) or g (pp=1)
        int g1 = g0 + HH;          // gate f or o
        int ka = 2 * k2, kb = 2 * k2 + 1;
        longlong2 v;
        v.x = (long long)pack2(W_hh0[g0 * HH + ka], W_hh0[g1 * HH + ka]);
        v.y = (long long)pack2(W_hh0[g0 * HH + kb], W_hh0[g1 * HH + kb]);
        g_W0p[t] = v;
        v.x = (long long)pack2(W_ih1[g0 * HH + ka], W_ih1[g1 * HH + ka]);
        v.y = (long long)pack2(W_ih1[g0 * HH + kb], W_ih1[g1 * HH + kb]);
        g_W1ip[t] = v;
        v.x = (long long)pack2(W_hh1[g0 * HH + ka], W_hh1[g1 * HH + ka]);
        v.y = (long long)pack2(W_hh1[g0 * HH + kb], W_hh1[g1 * HH + kb]);
        g_W1hp[t] = v;
    }
    if (idx < GG) {
        g_b0[idx] = b_ih0[idx] + b_hh0[idx];
        g_b1[idx] = b_ih1[idx] + b_hh1[idx];
    }
}

// one pass of accumulation against weight array WARR and dup'd-h buffer HIN
#define KLOOP(WARR, HIN)                                                       \
    {                                                                          \
        const longlong2* p = (WARR) + j;                                       \
        const longlong2* hp = (const longlong2*)((HIN) + mb);                  \
        _Pragma("unroll 2") for (int k2 = 0; k2 < NK2; k2++) {                 \
            longlong2 wif = p[0], wgo = p[HH];                                 \
            p += 2 * HH;                                                       \
            longlong2 a0 = hp[0], a1 = hp[1];                                  \
            longlong2 b0 = hp[HROW / 2], b1 = hp[HROW / 2 + 1];                \
            hp += HROW;                                                        \
            aif[0] = fma2((u64)wif.x, (u64)a0.x, aif[0]);                      \
            ago[0] = fma2((u64)wgo.x, (u64)a0.x, ago[0]);                      \
            aif[1] = fma2((u64)wif.x, (u64)a0.y, aif[1]);                      \
            ago[1] = fma2((u64)wgo.x, (u64)a0.y, ago[1]);                      \
            aif[2] = fma2((u64)wif.x, (u64)a1.x, aif[2]);                      \
            ago[2] = fma2((u64)wgo.x, (u64)a1.x, ago[2]);                      \
            aif[3] = fma2((u64)wif.x, (u64)a1.y, aif[3]);                      \
            ago[3] = fma2((u64)wgo.x, (u64)a1.y, ago[3]);                      \
            aif[0] = fma2((u64)wif.y, (u64)b0.x, aif[0]);                      \
            ago[0] = fma2((u64)wgo.y, (u64)b0.x, ago[0]);                      \
            aif[1] = fma2((u64)wif.y, (u64)b0.y, aif[1]);                      \
            ago[1] = fma2((u64)wgo.y, (u64)b0.y, ago[1]);                      \
            aif[2] = fma2((u64)wif.y, (u64)b1.x, aif[2]);                      \
            ago[2] = fma2((u64)wgo.y, (u64)b1.x, ago[2]);                      \
            aif[3] = fma2((u64)wif.y, (u64)b1.y, aif[3]);                      \
            ago[3] = fma2((u64)wgo.y, (u64)b1.y, ago[3]);                      \
        }                                                                      \
    }

// activations + cell update + dup'd h store (one STS.128)
#define ACT(CC, HOUT)                                                          \
    {                                                                          \
        _Pragma("unroll") for (int i = 0; i < MH / 2; i++) {                   \
            float zi0, zf0, zg0, zo0, zi1, zf1, zg1, zo1;                      \
            unpack2(aif[2 * i], zi0, zf0);                                     \
            unpack2(ago[2 * i], zg0, zo0);                                     \
            unpack2(aif[2 * i + 1], zi1, zf1);                                 \
            unpack2(ago[2 * i + 1], zg1, zo1);                                 \
            float cA = fmaf(sigf(zf0), (CC)[2 * i], sigf(zi0) * tanhx(zg0));   \
            float cB =                                                         \
                fmaf(sigf(zf1), (CC)[2 * i + 1], sigf(zi1) * tanhx(zg1));      \
            (CC)[2 * i] = cA;                                                  \
            (CC)[2 * i + 1] = cB;                                              \
            longlong2 st;                                                      \
            st.x = (long long)dup2(sigf(zo0) * tanhx(cA));                     \
            st.y = (long long)dup2(sigf(zo1) * tanhx(cB));                     \
            ((longlong2*)((HOUT) + j * HROW + mb))[i] = st;                    \
        }                                                                      \
    }

// -------- main LSTM kernel: 1024 threads = 256 units x 4 batch quarters --------
__global__ __launch_bounds__(NTH, 1)
void lstm_kernel(const float* __restrict__ x,
                 const float* __restrict__ W_ih0,
                 const float* __restrict__ W_fc,
                 const float* __restrict__ b_fc,
                 float* __restrict__ out) {
    extern __shared__ u64 dsm[];
    u64* sh1 = dsm;                  // [2][HH][HROW] layer0 h (dup pairs)
    u64* sh2 = dsm + 2 * HS;         // [2][HH][HROW] layer1 h
    u64* sbias = sh2 + 2 * HS;       // [4][HH]: bif0,bgo0,bif1,bgo1
    u64* swih = sbias + 4 * HH;      // [8][HH]: packed W_ih0 pairs per d
    float* xs = (float*)(swih + 8 * HH);  // [2][MM*DD] double-buffered x

    const int tid  = threadIdx.x;
    const int j    = tid & (HH - 1);  // hidden unit
    const int mb   = (tid >> 8) * MH; // batch quarter base (warp-uniform)
    const int row0 = blockIdx.x * MM;

    // one-time init
    for (int i = tid; i < 4 * HS; i += NTH) dsm[i] = 0ull;
    if (tid < HH) {
        sbias[tid]          = pack2(g_b0[tid], g_b0[tid + HH]);
        sbias[HH + tid]     = pack2(g_b0[tid + 2 * HH], g_b0[tid + 3 * HH]);
        sbias[2 * HH + tid] = pack2(g_b1[tid], g_b1[tid + HH]);
        sbias[3 * HH + tid] = pack2(g_b1[tid + 2 * HH], g_b1[tid + 3 * HH]);
#pragma unroll
        for (int d = 0; d < DD; d++) {
            swih[d * HH + tid] =
                pack2(W_ih0[tid * DD + d], W_ih0[(tid + HH) * DD + d]);
            swih[(4 + d) * HH + tid] =
                pack2(W_ih0[(tid + 2 * HH) * DD + d], W_ih0[(tid + 3 * HH) * DD + d]);
        }
    }
    if (tid < MM * DD)
        xs[tid] = x[(size_t)(row0 + (tid >> 2)) * (TT * DD) + (tid & 3)];
    __syncthreads();

    float c1[MH] = {0.f, 0.f, 0.f, 0.f};
    float c2[MH] = {0.f, 0.f, 0.f, 0.f};

    for (int t = 0; t < TT; t++) {
        const u64* h1in = sh1 + ((t + 1) & 1) * HS;  // h1(t-1)
        u64* h1out      = sh1 + (t & 1) * HS;        // h1(t)
        const u64* h2in = sh2 + ((t + 1) & 1) * HS;  // h2(t-1)
        u64* h2out      = sh2 + (t & 1) * HS;        // h2(t)
        const float* xc = xs + (t & 1) * (MM * DD);

        // prefetch next-step x (warps 0-1)
        float xreg = 0.0f;
        const bool doPref = (tid < MM * DD) && (t + 1 < TT);
        if (doPref)
            xreg = x[(size_t)(row0 + (tid >> 2)) * (TT * DD) + (t + 1) * DD + (tid & 3)];

        // ===== Layer 0 =====
        u64 aif[MH], ago[MH];
        {
            u64 ba = sbias[j], bb = sbias[HH + j];
#pragma unroll
            for (int m = 0; m < MH; m++) {
                u64 zif = ba, zgo = bb;
#pragma unroll
                for (int d = 0; d < DD; d++) {
                    u64 xd = dup2(xc[(mb + m) * DD + d]);
                    zif = fma2(swih[d * HH + j], xd, zif);
                    zgo = fma2(swih[(4 + d) * HH + j], xd, zgo);
                }
                aif[m] = zif;
                ago[m] = zgo;
            }
        }
        KLOOP(g_W0p, h1in)
        ACT(c1, h1out)
        __syncthreads();  // h1out(t) visible

        // ===== Layer 1 (two passes, acc persists) =====
        {
            u64 ba = sbias[2 * HH + j], bb = sbias[3 * HH + j];
#pragma unroll
            for (int m = 0; m < MH; m++) {
                aif[m] = ba;
                ago[m] = bb;
            }
        }
        KLOOP(g_W1ip, h1out)
        KLOOP(g_W1hp, h2in)
        ACT(c2, h2out)

        if (doPref) xs[((t + 1) & 1) * (MM * DD) + tid] = xreg;
        __syncthreads();  // h2out(t) + next x visible; h-in buffers free
    }

    // ---- FC epilogue: h2(199) lives in sh2 buffer (199&1)=1 ----
    if (tid < MM * OO) {
        int m = tid / OO;
        int o = tid % OO;
        const float* h2f = (const float*)(sh2 + 1 * HS);
        float s = b_fc[o];
#pragma unroll 4
        for (int k = 0; k < HH; k++)
            s = fmaf(h2f[(k * HROW + m) * 2], W_fc[o * HH + k], s);
        out[(row0 + m) * OO + o] = s;
    }
}

extern "C" void kernel_launch(void* const* d_in, const int* in_sizes, int n_in,
                              void* d_out, int out_size) {
    const float* x     = (const float*)d_in[0];
    const float* W_ih0 = (const float*)d_in[1];
    const float* W_hh0 = (const float*)d_in[2];
    const float* b_ih0 = (const float*)d_in[3];
    const float* b_hh0 = (const float*)d_in[4];
    const float* W_ih1 = (const float*)d_in[5];
    const float* W_hh1 = (const float*)d_in[6];
    const float* b_ih1 = (const float*)d_in[7];
    const float* b_hh1 = (const float*)d_in[8];
    const float* W_fc  = (const float*)d_in[9];
    const float* b_fc  = (const float*)d_in[10];
    float* out = (float*)d_out;

    // smem: 4 h buffers + bias/W_ih0 tables + double-buffered x
    const int smem_bytes = (4 * HS + 12 * HH) * 8 + 2 * MM * DD * 4;  // ~172.5 KB
    cudaFuncSetAttribute(lstm_kernel, cudaFuncAttributeMaxDynamicSharedMemorySize,
                         smem_bytes);

    prep_kernel<<<256, 256>>>(W_hh0, W_ih1, W_hh1, b_ih0, b_hh0, b_ih1, b_hh1);
    lstm_kernel<<<NCTA, NTH, smem_bytes>>>(x, W_ih0, W_fc, b_fc, out);
}